// round 7
// baseline (speedup 1.0000x reference)
#include <cuda_runtime.h>
#include <cstdint>

// Chamfer distance, B=4,S=4 pairs, N=M=4096 Gaussian 3D points.
// Warp-uniform sorted-window exact NN, packed-record edition:
//  1) build_sorted: counting-sort the 32 lists by x into 256 bins over
//     [-5,5]; emits interleaved 32B records {x0,x1,y0,y1,z0,z1,h0,h1}
//     (h = 0.5*|p|^2) plus u16 bin starts. Pad records are sentinels.
//  2) chamfer_query: block copies the packed list (64KB) + bin starts to
//     smem. Each warp scans its union bin-window with a fully uniform
//     loop: 2x LDS.128 + 3x fma.rn.f32x2 + 2x FMNMX per 2 evals.
//     Ballot-driven exact expansion. Grid 416 blocks = ONE wave @3/SM.

#define BDIM 4
#define SDIM 4
#define NPAIRS 16
#define NB 256
#define MAXPTS 4096
#define NREC ((MAXPTS + 8) / 2)   /* 2052 records of 2 points */
#define GRIDMIN (-5.0f)
#define BW 0.0390625f             /* 10/256 */
#define INVBW 25.6f
#define QTHREADS 320

__device__ float g_packed[2 * NPAIRS][NREC * 8];
__device__ unsigned short g_start[2 * NPAIRS][NB + 1];

__device__ __forceinline__ uint64_t fma2(uint64_t a, uint64_t b, uint64_t c) {
    uint64_t d;
    asm("fma.rn.f32x2 %0, %1, %2, %3;" : "=l"(d) : "l"(a), "l"(b), "l"(c));
    return d;
}
__device__ __forceinline__ uint64_t pack2(float lo, float hi) {
    uint64_t d;
    asm("mov.b64 %0, {%1, %2};" : "=l"(d) : "f"(lo), "f"(hi));
    return d;
}
__device__ __forceinline__ void unpack2(uint64_t v, float& lo, float& hi) {
    asm("mov.b64 {%0, %1}, %2;" : "=f"(lo), "=f"(hi) : "l"(v));
}

// ---------------- counting sort by x into 256 bins ----------------
__global__ void build_sorted(const float* __restrict__ outp,
                             const float* __restrict__ tgtp,
                             int Nq, int Mt) {
    const int list = blockIdx.x;            // 0..31
    const int set = list >> 4, pair = list & 15;
    const float* pts = set ? tgtp : outp;
    const int n = set ? Mt : Nq;
    const float* base = pts + (size_t)pair * n * 3;

    __shared__ int cnt[NB];
    const int t = threadIdx.x;              // 256 threads

    cnt[t] = 0;
    __syncthreads();

    for (int i = t; i < n; i += NB) {
        float x = base[3 * i];
        int b = min(max(__float2int_rd((x - GRIDMIN) * INVBW), 0), NB - 1);
        atomicAdd(&cnt[b], 1);
    }
    __syncthreads();

    int v = cnt[t];
    __syncthreads();
#pragma unroll
    for (int off = 1; off < NB; off <<= 1) {
        int u = (t >= off) ? cnt[t - off] : 0;
        __syncthreads();
        cnt[t] += u;
        __syncthreads();
    }
    int start = cnt[t] - v;  // exclusive

    g_start[list][t] = (unsigned short)start;
    if (t == 0) g_start[list][NB] = (unsigned short)n;

    __syncthreads();
    cnt[t] = start;
    __syncthreads();

    for (int i = t; i < n; i += NB) {
        float x = base[3 * i], y = base[3 * i + 1], z = base[3 * i + 2];
        int b = min(max(__float2int_rd((x - GRIDMIN) * INVBW), 0), NB - 1);
        int idx = atomicAdd(&cnt[b], 1);
        float* rec = &g_packed[list][(idx >> 1) * 8];
        int s = idx & 1;
        rec[0 + s] = x;
        rec[2 + s] = y;
        rec[4 + s] = z;
        rec[6 + s] = 0.5f * (x * x + y * y + z * z);
    }
    // sentinel pad points [n, 2*NREC)
    for (int i = n + t; i < 2 * NREC; i += NB) {
        float* rec = &g_packed[list][(i >> 1) * 8];
        int s = i & 1;
        rec[0 + s] = 1e30f;
        rec[2 + s] = 0.f;
        rec[4 + s] = 0.f;
        rec[6 + s] = 3.0e37f;
    }
}

// ---------------- query ----------------
extern __shared__ char smraw[];

// warp-uniform scan of even point range [a,b); each lane its own min
__device__ __forceinline__ void scan_range(
    int a, int b,
    uint64_t nx, uint64_t ny, uint64_t nz,
    const ulonglong2* __restrict__ recs,
    float& mlo, float& mhi) {
    const int j0 = a >> 1, j1 = b >> 1;
#pragma unroll 4
    for (int j = j0; j < j1; j++) {
        ulonglong2 A = recs[2 * j];      // {x2, y2}
        ulonglong2 B = recs[2 * j + 1];  // {z2, h2}
        uint64_t t = fma2(nx, A.x, B.y);
        t = fma2(ny, A.y, t);
        t = fma2(nz, B.x, t);
        float lo, hi;
        unpack2(t, lo, hi);
        mlo = fminf(mlo, lo);
        mhi = fminf(mhi, hi);
    }
}

__global__ __launch_bounds__(QTHREADS)
void chamfer_query(int Nq, int Mt, float* __restrict__ out) {
    const int dir = blockIdx.z;             // 0: out->tgt, 1: tgt->out
    const int pair = blockIdx.y;
    const int qlist = (dir ? NPAIRS : 0) + pair;      // own (sorted) set
    const int tlist = (dir ? 0 : NPAIRS) + pair;      // other set
    const int nq = dir ? Mt : Nq;

    // ---- stage packed target records (64KB copy) + bin starts ----
    uint4* dst = (uint4*)smraw;
    const uint4* src = (const uint4*)g_packed[tlist];
    for (int i = threadIdx.x; i < 2 * NREC; i += QTHREADS)
        dst[i] = src[i];
    unsigned short* sstart = (unsigned short*)(smraw + NREC * 32);
    for (int c = threadIdx.x; c <= NB; c += QTHREADS)
        sstart[c] = g_start[tlist][c];
    __syncthreads();

    const ulonglong2* recs = (const ulonglong2*)smraw;

    const int qi = blockIdx.x * QTHREADS + threadIdx.x;
    const bool active = (qi < nq);

    float qx = 0.f, q2 = 0.f;
    uint64_t nx = 0, ny = 0, nz = 0;
    int qb = 0x7fffffff, qb2 = -1;
    if (active) {
        const float* qr = &g_packed[qlist][(qi >> 1) * 8];
        int s = qi & 1;
        qx = qr[0 + s];
        float qy = qr[2 + s], qz = qr[4 + s];
        q2 = qx * qx + qy * qy + qz * qz;
        nx = pack2(-qx, -qx);
        ny = pack2(-qy, -qy);
        nz = pack2(-qz, -qz);
        qb = min(max(__float2int_rd((qx - GRIDMIN) * INVBW), 0), NB - 1);
        qb2 = qb;
    }
    float mlo = 3.0e37f, mhi = 3.0e37f;

    // warp-union window (warp-uniform); inactive lanes neutral
    int BL = qb, BR = qb2;
#pragma unroll
    for (int off = 16; off; off >>= 1) {
        BL = min(BL, __shfl_xor_sync(0xffffffffu, BL, off));
        BR = max(BR, __shfl_xor_sync(0xffffffffu, BR, off));
    }

    if (BR >= 0) {  // warp has at least one active lane
        BL = max(BL - 3, 0);
        BR = min(BR + 4, NB);

        int LO = sstart[BL] & ~1;
        int HI = (sstart[BR] + 1) & ~1;
        scan_range(LO, HI, nx, ny, nz, recs, mlo, mhi);

        // ---- ballot-driven warp-uniform expansion ----
        for (int iter = 0; iter < NB; iter++) {
            float best = fmaxf(fmaf(2.0f, fminf(mlo, mhi), q2), 0.0f);
            float lb = fmaxf(qx - (GRIDMIN + BL * BW) - 1e-4f, 0.0f);
            float rb = fmaxf((GRIDMIN + BR * BW) - qx - 1e-4f, 0.0f);
            bool needL = active && (BL > 0)  && (lb * lb < best);
            bool needR = active && (BR < NB) && (rb * rb < best);
            unsigned anyL = __ballot_sync(0xffffffffu, needL);
            unsigned anyR = __ballot_sync(0xffffffffu, needR);
            if (!anyL && !anyR) break;
            if (anyL) {
                int nBL = BL - 1;
                int nLO = sstart[nBL] & ~1;
                scan_range(nLO, LO, nx, ny, nz, recs, mlo, mhi);
                BL = nBL; LO = nLO;
            }
            if (anyR) {
                int nBR = BR + 1;
                int nHI = (sstart[nBR] + 1) & ~1;
                scan_range(HI, nHI, nx, ny, nz, recs, mlo, mhi);
                BR = nBR; HI = nHI;
            }
        }
    }

    float lsum = active ? fmaxf(fmaf(2.0f, fminf(mlo, mhi), q2), 0.0f) : 0.f;

    // ---- block reduce + one atomicAdd ----
#pragma unroll
    for (int off = 16; off; off >>= 1)
        lsum += __shfl_down_sync(0xffffffffu, lsum, off);
    __shared__ float red[QTHREADS / 32];
    const int wid = threadIdx.x >> 5;
    if ((threadIdx.x & 31) == 0) red[wid] = lsum;
    __syncthreads();
    if (threadIdx.x == 0) {
        float tot = 0.f;
#pragma unroll
        for (int w = 0; w < QTHREADS / 32; w++) tot += red[w];
        int b = pair / SDIM;
        int s = pair % SDIM;
        atomicAdd(out + s * BDIM + b, tot / (float)nq);
    }
}

extern "C" void kernel_launch(void* const* d_in, const int* in_sizes, int n_in,
                              void* d_out, int out_size) {
    const float* outp = (const float*)d_in[0];  // [B,S,N,3]
    const float* tgtp = (const float*)d_in[1];  // [B,S,M,3]
    float* out = (float*)d_out;                  // [S,B]

    const int Nq = in_sizes[0] / (NPAIRS * 3);
    const int Mt = in_sizes[1] / (NPAIRS * 3);

    cudaMemsetAsync(out, 0, (size_t)out_size * sizeof(float));

    build_sorted<<<2 * NPAIRS, NB>>>(outp, tgtp, Nq, Mt);

    const size_t smem = (size_t)NREC * 32 + (NB + 2) * sizeof(unsigned short);
    cudaFuncSetAttribute(chamfer_query,
                         cudaFuncAttributeMaxDynamicSharedMemorySize, (int)smem);

    const int maxq = Nq > Mt ? Nq : Mt;
    // 13 chunks x 320 thr covers 4096 queries; 416 blocks = single wave @3/SM
    dim3 grid((maxq + QTHREADS - 1) / QTHREADS, NPAIRS, 2);
    chamfer_query<<<grid, QTHREADS, smem>>>(Nq, Mt, out);
}

// round 8
// speedup vs baseline: 1.0274x; 1.0274x over previous
#include <cuda_runtime.h>
#include <cstdint>

// Chamfer distance, B=4,S=4 pairs, N=M=4096 Gaussian 3D points.
// Warp-uniform sorted-window exact NN, packed records + balanced blocks:
//  1) build_sorted: counting-sort the 32 lists by x into 256 bins over
//     [-5,5]; emits interleaved 32B records {x0,x1,y0,y1,z0,z1,h0,h1}
//     (h = 0.5*|p|^2) plus u16 bin starts. Pad records are sentinels.
//  2) chamfer_query: block copies the packed target list (64KB) + bin
//     starts to smem. Each warp owns 32 CONSECUTIVE sorted queries
//     (coherent window) but warps are assigned to blocks with STRIDE 13
//     across the sorted order, so every block carries a near-equal mix of
//     dense-center and sparse-edge windows (load balance across SMs).
//     Inner loop: 2x LDS.128 + 3x fma.rn.f32x2 + 2x FMNMX per 2 evals.
//     Ballot-driven exact expansion.

#define BDIM 4
#define SDIM 4
#define NPAIRS 16
#define NB 256
#define MAXPTS 4096
#define NREC ((MAXPTS + 8) / 2)   /* 2052 records of 2 points */
#define GRIDMIN (-5.0f)
#define BW 0.0390625f             /* 10/256 */
#define INVBW 25.6f
#define QTHREADS 320
#define NCHUNK 13                 /* blocks per (dir,pair); 13*10 >= 128 warps */

__device__ float g_packed[2 * NPAIRS][NREC * 8];
__device__ unsigned short g_start[2 * NPAIRS][NB + 1];

__device__ __forceinline__ uint64_t fma2(uint64_t a, uint64_t b, uint64_t c) {
    uint64_t d;
    asm("fma.rn.f32x2 %0, %1, %2, %3;" : "=l"(d) : "l"(a), "l"(b), "l"(c));
    return d;
}
__device__ __forceinline__ uint64_t pack2(float lo, float hi) {
    uint64_t d;
    asm("mov.b64 %0, {%1, %2};" : "=l"(d) : "f"(lo), "f"(hi));
    return d;
}
__device__ __forceinline__ void unpack2(uint64_t v, float& lo, float& hi) {
    asm("mov.b64 {%0, %1}, %2;" : "=f"(lo), "=f"(hi) : "l"(v));
}

// ---------------- counting sort by x into 256 bins ----------------
__global__ void build_sorted(const float* __restrict__ outp,
                             const float* __restrict__ tgtp,
                             int Nq, int Mt) {
    const int list = blockIdx.x;            // 0..31
    const int set = list >> 4, pair = list & 15;
    const float* pts = set ? tgtp : outp;
    const int n = set ? Mt : Nq;
    const float* base = pts + (size_t)pair * n * 3;

    __shared__ int cnt[NB];
    const int t = threadIdx.x;              // 256 threads

    cnt[t] = 0;
    __syncthreads();

    for (int i = t; i < n; i += NB) {
        float x = base[3 * i];
        int b = min(max(__float2int_rd((x - GRIDMIN) * INVBW), 0), NB - 1);
        atomicAdd(&cnt[b], 1);
    }
    __syncthreads();

    int v = cnt[t];
    __syncthreads();
#pragma unroll
    for (int off = 1; off < NB; off <<= 1) {
        int u = (t >= off) ? cnt[t - off] : 0;
        __syncthreads();
        cnt[t] += u;
        __syncthreads();
    }
    int start = cnt[t] - v;  // exclusive

    g_start[list][t] = (unsigned short)start;
    if (t == 0) g_start[list][NB] = (unsigned short)n;

    __syncthreads();
    cnt[t] = start;
    __syncthreads();

    for (int i = t; i < n; i += NB) {
        float x = base[3 * i], y = base[3 * i + 1], z = base[3 * i + 2];
        int b = min(max(__float2int_rd((x - GRIDMIN) * INVBW), 0), NB - 1);
        int idx = atomicAdd(&cnt[b], 1);
        float* rec = &g_packed[list][(idx >> 1) * 8];
        int s = idx & 1;
        rec[0 + s] = x;
        rec[2 + s] = y;
        rec[4 + s] = z;
        rec[6 + s] = 0.5f * (x * x + y * y + z * z);
    }
    // sentinel pad points [n, 2*NREC)
    for (int i = n + t; i < 2 * NREC; i += NB) {
        float* rec = &g_packed[list][(i >> 1) * 8];
        int s = i & 1;
        rec[0 + s] = 1e30f;
        rec[2 + s] = 0.f;
        rec[4 + s] = 0.f;
        rec[6 + s] = 3.0e37f;
    }
}

// ---------------- query ----------------
extern __shared__ char smraw[];

// warp-uniform scan of even point range [a,b); each lane its own min
__device__ __forceinline__ void scan_range(
    int a, int b,
    uint64_t nx, uint64_t ny, uint64_t nz,
    const ulonglong2* __restrict__ recs,
    float& mlo, float& mhi) {
    const int j0 = a >> 1, j1 = b >> 1;
#pragma unroll 4
    for (int j = j0; j < j1; j++) {
        ulonglong2 A = recs[2 * j];      // {x2, y2}
        ulonglong2 B = recs[2 * j + 1];  // {z2, h2}
        uint64_t t = fma2(nx, A.x, B.y);
        t = fma2(ny, A.y, t);
        t = fma2(nz, B.x, t);
        float lo, hi;
        unpack2(t, lo, hi);
        mlo = fminf(mlo, lo);
        mhi = fminf(mhi, hi);
    }
}

__global__ __launch_bounds__(QTHREADS)
void chamfer_query(int Nq, int Mt, float* __restrict__ out) {
    const int dir = blockIdx.z;             // 0: out->tgt, 1: tgt->out
    const int pair = blockIdx.y;
    const int qlist = (dir ? NPAIRS : 0) + pair;      // own (sorted) set
    const int tlist = (dir ? 0 : NPAIRS) + pair;      // other set
    const int nq = dir ? Mt : Nq;

    // ---- stage packed target records (64KB copy) + bin starts ----
    uint4* dst = (uint4*)smraw;
    const uint4* src = (const uint4*)g_packed[tlist];
    for (int i = threadIdx.x; i < 2 * NREC; i += QTHREADS)
        dst[i] = src[i];
    unsigned short* sstart = (unsigned short*)(smraw + NREC * 32);
    for (int c = threadIdx.x; c <= NB; c += QTHREADS)
        sstart[c] = g_start[tlist][c];
    __syncthreads();

    const ulonglong2* recs = (const ulonglong2*)smraw;

    // warp w of this block owns query-warp (blockIdx.x + NCHUNK*w):
    // 32 consecutive sorted queries (coherent window), but blocks sample
    // the sorted order with stride NCHUNK -> balanced block workloads.
    const int lwid = threadIdx.x >> 5;
    const int lane = threadIdx.x & 31;
    const int qwarp = blockIdx.x + NCHUNK * lwid;
    const int qi = qwarp * 32 + lane;
    const bool active = (qi < nq);

    float qx = 0.f, q2 = 0.f;
    uint64_t nx = 0, ny = 0, nz = 0;
    int qb = 0x7fffffff, qb2 = -1;
    if (active) {
        const float* qr = &g_packed[qlist][(qi >> 1) * 8];
        int s = qi & 1;
        qx = qr[0 + s];
        float qy = qr[2 + s], qz = qr[4 + s];
        q2 = qx * qx + qy * qy + qz * qz;
        nx = pack2(-qx, -qx);
        ny = pack2(-qy, -qy);
        nz = pack2(-qz, -qz);
        qb = min(max(__float2int_rd((qx - GRIDMIN) * INVBW), 0), NB - 1);
        qb2 = qb;
    }
    float mlo = 3.0e37f, mhi = 3.0e37f;

    // warp-union window (warp-uniform); inactive lanes neutral
    int BL = qb, BR = qb2;
#pragma unroll
    for (int off = 16; off; off >>= 1) {
        BL = min(BL, __shfl_xor_sync(0xffffffffu, BL, off));
        BR = max(BR, __shfl_xor_sync(0xffffffffu, BR, off));
    }

    if (BR >= 0) {  // warp has at least one active lane
        BL = max(BL - 3, 0);
        BR = min(BR + 4, NB);

        int LO = sstart[BL] & ~1;
        int HI = (sstart[BR] + 1) & ~1;
        scan_range(LO, HI, nx, ny, nz, recs, mlo, mhi);

        // ---- ballot-driven warp-uniform expansion ----
        for (int iter = 0; iter < NB; iter++) {
            float best = fmaxf(fmaf(2.0f, fminf(mlo, mhi), q2), 0.0f);
            float lb = fmaxf(qx - (GRIDMIN + BL * BW) - 1e-4f, 0.0f);
            float rb = fmaxf((GRIDMIN + BR * BW) - qx - 1e-4f, 0.0f);
            bool needL = active && (BL > 0)  && (lb * lb < best);
            bool needR = active && (BR < NB) && (rb * rb < best);
            unsigned anyL = __ballot_sync(0xffffffffu, needL);
            unsigned anyR = __ballot_sync(0xffffffffu, needR);
            if (!anyL && !anyR) break;
            if (anyL) {
                int nBL = BL - 1;
                int nLO = sstart[nBL] & ~1;
                scan_range(nLO, LO, nx, ny, nz, recs, mlo, mhi);
                BL = nBL; LO = nLO;
            }
            if (anyR) {
                int nBR = BR + 1;
                int nHI = (sstart[nBR] + 1) & ~1;
                scan_range(HI, nHI, nx, ny, nz, recs, mlo, mhi);
                BR = nBR; HI = nHI;
            }
        }
    }

    float lsum = active ? fmaxf(fmaf(2.0f, fminf(mlo, mhi), q2), 0.0f) : 0.f;

    // ---- block reduce + one atomicAdd ----
#pragma unroll
    for (int off = 16; off; off >>= 1)
        lsum += __shfl_down_sync(0xffffffffu, lsum, off);
    __shared__ float red[QTHREADS / 32];
    const int wid = threadIdx.x >> 5;
    if ((threadIdx.x & 31) == 0) red[wid] = lsum;
    __syncthreads();
    if (threadIdx.x == 0) {
        float tot = 0.f;
#pragma unroll
        for (int w = 0; w < QTHREADS / 32; w++) tot += red[w];
        int b = pair / SDIM;
        int s = pair % SDIM;
        atomicAdd(out + s * BDIM + b, tot / (float)nq);
    }
}

extern "C" void kernel_launch(void* const* d_in, const int* in_sizes, int n_in,
                              void* d_out, int out_size) {
    const float* outp = (const float*)d_in[0];  // [B,S,N,3]
    const float* tgtp = (const float*)d_in[1];  // [B,S,M,3]
    float* out = (float*)d_out;                  // [S,B]

    const int Nq = in_sizes[0] / (NPAIRS * 3);
    const int Mt = in_sizes[1] / (NPAIRS * 3);

    cudaMemsetAsync(out, 0, (size_t)out_size * sizeof(float));

    build_sorted<<<2 * NPAIRS, NB>>>(outp, tgtp, Nq, Mt);

    const size_t smem = (size_t)NREC * 32 + (NB + 2) * sizeof(unsigned short);
    cudaFuncSetAttribute(chamfer_query,
                         cudaFuncAttributeMaxDynamicSharedMemorySize, (int)smem);

    // NCHUNK blocks per (dir,pair), warps strided across the sorted order
    dim3 grid(NCHUNK, NPAIRS, 2);  // 416 blocks, single wave @3/SM
    chamfer_query<<<grid, QTHREADS, smem>>>(Nq, Mt, out);
}